// round 13
// baseline (speedup 1.0000x reference)
#include <cuda_runtime.h>

#define NN 100000
#define NE 800000
#define IC 96
#define OC 64
#define GN 64             // nodes per GEMM block
#define CHUNK 1024        // scan chunk
#define NB ((NN + CHUNK - 1) / CHUNK)   // 98
static_assert(NB <= 128, "lookback scan assumes <=128 chunks");

// ---- scratch (static device globals; zero-initialized at module load) ----
// Referenced only from device code; never passed as kernel arguments.
// INVARIANT: every full pipeline execution leaves g_cnt[] and g_pub[] zeroed
// (done in the hop-2 gather), so graph replays start from a clean state.
__device__ float g_dinv[NN];
__device__ int   g_cnt[NN];       // in-degree; re-zeroed by hop-2 gather
__device__ int   g_rowstart[NN];
__device__ int   g_cursor[NN];
__device__ int   g_pub[128];      // lookback: chunk aggregate + 1 (0 = not ready)
__device__ __align__(16) int2  g_sw[NE];       // CSR-by-dest: (src, weight-bits)
__device__ __align__(16) float g_A[NN * OC];   // h = x W^T, hop-1 source
__device__ __align__(16) float g_B[NN * OC];   // hop-1 result / hop-2 source

// ---------------------------------------------------------------- per-block dtype detect
// int64 little-endian values < 2^31 => all odd int32 words of the first 64
// entries are zero. 64 L2-hit loads by thread 0, broadcast via smem.
__device__ __forceinline__ int detect_is64(const int* __restrict__ ei32, int* s_flag) {
    if (threadIdx.x == 0) {
        int nz = 0;
        #pragma unroll 8
        for (int k = 0; k < 64; k++) nz |= ei32[2 * k + 1];
        *s_flag = (nz == 0) ? 1 : 0;
    }
    __syncthreads();
    return *s_flag;
}

// ---------------------------------------------------------------- count in-degree (c only)
__global__ void k_count(const int* __restrict__ ei32) {
    __shared__ int s_is64;
    int is64 = detect_is64(ei32, &s_is64);
    int e = blockIdx.x * blockDim.x + threadIdx.x;
    if (e < NE) {
        int c = is64 ? ei32[2 * (NE + e)] : ei32[NE + e];
        if ((unsigned)c < NN) atomicAdd(&g_cnt[c], 1);
    }
}

// ---------------------------------------------------------------- single-pass scan (decoupled lookback)
// Per chunk of 1024 nodes: local exclusive scan + dinv, publish aggregate,
// sum predecessor aggregates, write final rowstart + cursor.
__global__ void __launch_bounds__(256) k_scan() {
    __shared__ int s[256];
    __shared__ int s2[256];
    int t = threadIdx.x, b = blockIdx.x;
    int base = b * CHUNK + t * 4;

    int v0 = (base + 0 < NN) ? g_cnt[base + 0] : 0;
    int v1 = (base + 1 < NN) ? g_cnt[base + 1] : 0;
    int v2 = (base + 2 < NN) ? g_cnt[base + 2] : 0;
    int v3 = (base + 3 < NN) ? g_cnt[base + 3] : 0;
    // dinv while cnt is hot (deg includes +1 self loop)
    if (base + 0 < NN) g_dinv[base + 0] = rsqrtf((float)v0 + 1.0f);
    if (base + 1 < NN) g_dinv[base + 1] = rsqrtf((float)v1 + 1.0f);
    if (base + 2 < NN) g_dinv[base + 2] = rsqrtf((float)v2 + 1.0f);
    if (base + 3 < NN) g_dinv[base + 3] = rsqrtf((float)v3 + 1.0f);

    int sum = v0 + v1 + v2 + v3;
    s[t] = sum;
    __syncthreads();
    for (int off = 1; off < 256; off <<= 1) {
        int add = (t >= off) ? s[t - off] : 0;
        __syncthreads();
        s[t] += add;
        __syncthreads();
    }
    int excl = s[t] - sum;          // exclusive within chunk

    // publish chunk aggregate (flag-encoded single word: agg+1; atomics are L2-coherent)
    if (t == 255) atomicExch(&g_pub[b], s[255] + 1);

    // lookback: thread t (< b) fetches predecessor t's aggregate
    int pre = 0;
    if (t < b) {
        int p;
        do { p = atomicAdd(&g_pub[t], 0); } while (p == 0);
        pre = p - 1;
    }
    s2[t] = pre;
    __syncthreads();
    for (int off = 128; off >= 1; off >>= 1) {
        if (t < off) s2[t] += s2[t + off];
        __syncthreads();
    }
    int P = s2[0];                  // exclusive prefix of this chunk

    int rs0 = P + excl;
    int rs1 = rs0 + v0;
    int rs2 = rs1 + v1;
    int rs3 = rs2 + v2;
    if (base + 0 < NN) { g_rowstart[base + 0] = rs0; g_cursor[base + 0] = rs0; }
    if (base + 1 < NN) { g_rowstart[base + 1] = rs1; g_cursor[base + 1] = rs1; }
    if (base + 2 < NN) { g_rowstart[base + 2] = rs2; g_cursor[base + 2] = rs2; }
    if (base + 3 < NN) { g_rowstart[base + 3] = rs3; g_cursor[base + 3] = rs3; }
}

// ---------------------------------------------------------------- CSR fill: packed (src, weight)
__global__ void k_fill(const int* __restrict__ ei32) {
    __shared__ int s_is64;
    int is64 = detect_is64(ei32, &s_is64);
    int e = blockIdx.x * blockDim.x + threadIdx.x;
    if (e < NE) {
        int r, c;
        if (is64) { r = ei32[2 * e]; c = ei32[2 * (NE + e)]; }
        else      { r = ei32[e];     c = ei32[NE + e]; }
        if ((unsigned)r < NN && (unsigned)c < NN) {
            int pos = atomicAdd(&g_cursor[c], 1);
            float w = g_dinv[r] * g_dinv[c];
            g_sw[pos] = make_int2(r, __float_as_int(w));
        }
    }
}

// ---------------------------------------------------------------- GEMM: g_A = x W^T
// 64 nodes x 64 oc per block, 256 threads, each thread 4n x 4oc (16 acc).
__global__ void __launch_bounds__(256) k_gemm(const float* __restrict__ x,
                                              const float* __restrict__ W) {
    __shared__ float Ws[IC][OC + 4];    // [96][68] padded
    __shared__ float xs[GN][IC + 4];    // [64][100] padded
    int tid = threadIdx.x;
    int b0  = blockIdx.x * GN;

    for (int i = tid; i < OC * IC; i += 256) {      // W[oc][k] -> Ws[k][oc]
        int oc = i / IC, k = i % IC;
        Ws[k][oc] = W[i];
    }
    for (int i = tid; i < GN * (IC / 4); i += 256) {   // x tile, float4 loads
        int n = i / (IC / 4), q = i % (IC / 4);
        int gn = b0 + n;
        float4 v = (gn < NN) ? ((const float4*)x)[(size_t)gn * (IC / 4) + q]
                             : make_float4(0.f, 0.f, 0.f, 0.f);
        *(float4*)&xs[n][q * 4] = v;
    }
    __syncthreads();

    int ocq = (tid & 15) * 4;      // oc quad base
    int n0  = (tid >> 4) * 4;      // node quad base
    float acc[4][4] = {};

    #pragma unroll 8
    for (int k = 0; k < IC; k++) {
        float4 w = *(const float4*)&Ws[k][ocq];
        #pragma unroll
        for (int i = 0; i < 4; i++) {
            float xv = xs[n0 + i][k];
            acc[i][0] += xv * w.x; acc[i][1] += xv * w.y;
            acc[i][2] += xv * w.z; acc[i][3] += xv * w.w;
        }
    }

    #pragma unroll
    for (int i = 0; i < 4; i++) {
        int gn = b0 + n0 + i;
        if (gn < NN)
            *(float4*)&g_A[(size_t)gn * OC + ocq] =
                make_float4(acc[i][0], acc[i][1], acc[i][2], acc[i][3]);
    }
}

// ---------------------------------------------------------------- gather hops
// 2 nodes per warp (half-warp of 16 lanes x float4 = full 256B row per node).
// Unroll-4: 4 edge chains in flight per node => MLP ~8 per warp.
// D[d] = dinv[d]^2 * S[d] + sum_{e: col=d} w_e * S[src_e]
// HOP2=false: S=g_A, D=g_B. HOP2=true: S=g_B, D=out (+bias+sigmoid) and
// state cleanup for the next graph replay (g_cnt, g_pub -> 0).
template <bool HOP2>
__global__ void k_gather(float* __restrict__ out, const float* __restrict__ bias) {
    int gid  = blockIdx.x * blockDim.x + threadIdx.x;
    int warp = gid >> 5;
    int node = (warp << 1) | ((threadIdx.x >> 4) & 1);
    if (node >= NN) return;
    int l = threadIdx.x & 15;

    const float4* __restrict__ Sp = (const float4*)(HOP2 ? g_B : g_A);
    float dd = g_dinv[node]; dd *= dd;
    float4 a = Sp[(size_t)node * 16 + l];
    float ax = a.x * dd, ay = a.y * dd, az = a.z * dd, aw = a.w * dd;

    int st  = g_rowstart[node];
    int cnt = g_cnt[node];
    int j = 0;
    for (; j + 4 <= cnt; j += 4) {
        int2 e0 = g_sw[st + j];
        int2 e1 = g_sw[st + j + 1];
        int2 e2 = g_sw[st + j + 2];
        int2 e3 = g_sw[st + j + 3];
        float4 v0 = Sp[(size_t)e0.x * 16 + l];
        float4 v1 = Sp[(size_t)e1.x * 16 + l];
        float4 v2 = Sp[(size_t)e2.x * 16 + l];
        float4 v3 = Sp[(size_t)e3.x * 16 + l];
        float w0 = __int_as_float(e0.y), w1 = __int_as_float(e1.y);
        float w2 = __int_as_float(e2.y), w3 = __int_as_float(e3.y);
        ax += w0 * v0.x + w1 * v1.x + w2 * v2.x + w3 * v3.x;
        ay += w0 * v0.y + w1 * v1.y + w2 * v2.y + w3 * v3.y;
        az += w0 * v0.z + w1 * v1.z + w2 * v2.z + w3 * v3.z;
        aw += w0 * v0.w + w1 * v1.w + w2 * v2.w + w3 * v3.w;
    }
    for (; j < cnt; j++) {
        int2 e0 = g_sw[st + j];
        float4 v0 = Sp[(size_t)e0.x * 16 + l];
        float w0 = __int_as_float(e0.y);
        ax += w0 * v0.x; ay += w0 * v0.y; az += w0 * v0.z; aw += w0 * v0.w;
    }

    if (HOP2) {
        float4 b = ((const float4*)bias)[l];
        ax = 1.0f / (1.0f + __expf(-(ax + b.x)));
        ay = 1.0f / (1.0f + __expf(-(ay + b.y)));
        az = 1.0f / (1.0f + __expf(-(az + b.z)));
        aw = 1.0f / (1.0f + __expf(-(aw + b.w)));
        ((float4*)out)[(size_t)node * 16 + l] = make_float4(ax, ay, az, aw);
        // ---- state cleanup for next replay (after last read of g_cnt) ----
        if (l == 0) g_cnt[node] = 0;
        if (gid < 128) g_pub[gid] = 0;
    } else {
        ((float4*)g_B)[(size_t)node * 16 + l] = make_float4(ax, ay, az, aw);
    }
}

// ---------------------------------------------------------------- launch (6 kernels)
extern "C" void kernel_launch(void* const* d_in, const int* in_sizes, int n_in,
                              void* d_out, int out_size) {
    const float* x    = (const float*)d_in[0];
    const int*   ei32 = (const int*)d_in[1];   // raw words; dtype detected per block
    const float* W    = (const float*)d_in[2];
    const float* b    = (const float*)d_in[3];
    float*       out  = (float*)d_out;

    k_count<<<(NE + 255) / 256, 256>>>(ei32);
    k_scan <<<NB, 256>>>();
    k_fill <<<(NE + 255) / 256, 256>>>(ei32);

    k_gemm <<<(NN + GN - 1) / GN, 256>>>(x, W);

    // hop 1: g_B = P * g_A          (2 nodes per warp)
    k_gather<false><<<(NN / 2 * 32 + 255) / 256, 256>>>(nullptr, nullptr);
    // hop 2 + bias + sigmoid + replay-state cleanup
    k_gather<true> <<<(NN / 2 * 32 + 255) / 256, 256>>>(out, b);
}